// round 2
// baseline (speedup 1.0000x reference)
#include <cuda_runtime.h>

#define SS 512
#define EE 8
#define FF 4
#define FH 8   // F * num_heads

// Batch-independent precomputed cross-attention query-side terms:
// score[f,h,s] = x[s,:] . g_A[f*2+h,:] + g_c[f*2+h]
__device__ float g_A[FH][EE];
__device__ float g_c[FH];

__global__ void precompute_kernel(const float* __restrict__ Q,
                                  const float* __restrict__ sa_w_in,
                                  const float* __restrict__ sa_b_in,
                                  const float* __restrict__ sa_w_out,
                                  const float* __restrict__ sa_b_out,
                                  const float* __restrict__ ca_w_in,
                                  const float* __restrict__ ca_b_in) {
    // Single thread: self-attention over the 4 batch-identical factor queries,
    // then the cross-attention q-projection, folded with the k-projection.
    float qh[FF][EE], kh[FF][EE], vh[FF][EE];
    for (int f = 0; f < FF; f++)
        for (int ep = 0; ep < EE; ep++) {
            float aq = sa_b_in[ep], ak = sa_b_in[8 + ep], av = sa_b_in[16 + ep];
            for (int e = 0; e < EE; e++) {
                float qe = Q[f * EE + e];
                aq += qe * sa_w_in[ep * EE + e];
                ak += qe * sa_w_in[(8 + ep) * EE + e];
                av += qe * sa_w_in[(16 + ep) * EE + e];
            }
            qh[f][ep] = aq; kh[f][ep] = ak; vh[f][ep] = av;
        }
    float ctx[FF][EE];
    for (int h = 0; h < 2; h++)
        for (int f = 0; f < FF; f++) {
            float sc[FF];
            float mx = -1e30f;
            for (int m = 0; m < FF; m++) {
                float s = 0.f;
                for (int d = 0; d < 4; d++) s += qh[f][h * 4 + d] * kh[m][h * 4 + d];
                s *= 0.5f;  // 1/sqrt(Dh=4)
                sc[m] = s;
                mx = fmaxf(mx, s);
            }
            float sum = 0.f;
            for (int m = 0; m < FF; m++) { sc[m] = expf(sc[m] - mx); sum += sc[m]; }
            for (int d = 0; d < 4; d++) {
                float a = 0.f;
                for (int m = 0; m < FF; m++) a += sc[m] * vh[m][h * 4 + d];
                ctx[f][h * 4 + d] = a / sum;
            }
        }
    float qu[FF][EE];
    for (int f = 0; f < FF; f++)
        for (int ep = 0; ep < EE; ep++) {
            float a = sa_b_out[ep];
            for (int e = 0; e < EE; e++) a += ctx[f][e] * sa_w_out[ep * EE + e];
            qu[f][ep] = a;
        }
    // cross-attention q projection, pre-scaled by 1/sqrt(Dh)=0.5
    float qc[FF][EE];
    for (int f = 0; f < FF; f++)
        for (int ep = 0; ep < EE; ep++) {
            float a = ca_b_in[ep];
            for (int e = 0; e < EE; e++) a += qu[f][e] * ca_w_in[ep * EE + e];
            qc[f][ep] = a * 0.5f;
        }
    // fold q into k projection: A[f,h,e] = sum_d qc[f,h,d] * wk[h*4+d, e]
    for (int f = 0; f < FF; f++)
        for (int h = 0; h < 2; h++) {
            float c = 0.f;
            for (int d = 0; d < 4; d++) c += qc[f][h * 4 + d] * ca_b_in[8 + h * 4 + d];
            g_c[f * 2 + h] = c;
            for (int e = 0; e < EE; e++) {
                float a = 0.f;
                for (int d = 0; d < 4; d++) a += qc[f][h * 4 + d] * ca_w_in[(8 + h * 4 + d) * EE + e];
                g_A[f * 2 + h][e] = a;
            }
        }
}

__global__ __launch_bounds__(256) void afs_main_kernel(
    const float* __restrict__ x,
    const float* __restrict__ ca_w_in, const float* __restrict__ ca_b_in,
    const float* __restrict__ ca_w_out, const float* __restrict__ ca_b_out,
    const float* __restrict__ r_w1, const float* __restrict__ r_b1,
    const float* __restrict__ r_w2, const float* __restrict__ r_b2,
    float* __restrict__ outv, float* __restrict__ sim)
{
    __shared__ float sx[SS * EE];        // 16 KB: x tile
    __shared__ float ssc[FH][SS];        // 16 KB: cross-attn scores; reused for similarity
    __shared__ float sA[FH][EE];
    __shared__ float scc[FH];
    __shared__ float swv[EE][EE];
    __shared__ float sbv[EE];
    __shared__ float swo[EE][EE];
    __shared__ float sbo[EE];
    __shared__ float srw1[16 * 32];
    __shared__ float srb1[16];
    __shared__ float srw2[16];
    __shared__ float sctx[FF][EE];
    __shared__ float sqc[FF][EE];
    __shared__ float sfin[FF][EE];

    const int tid = threadIdx.x;
    const int b = blockIdx.x;
    const int w = tid >> 5, lane = tid & 31;

    // ---- load x[b] tile (16 KB, 1024 float4, coalesced) ----
    const float4* __restrict__ xin = (const float4*)(x + (size_t)b * (SS * EE));
    float4* sx4 = (float4*)sx;
#pragma unroll
    for (int i = 0; i < 4; i++) sx4[tid + 256 * i] = xin[tid + 256 * i];

    // ---- load small weights to smem ----
    if (tid < 64)       ((float*)sA)[tid]        = ((const float*)g_A)[tid];
    else if (tid < 72)  scc[tid - 64]            = g_c[tid - 64];
    else if (tid < 136) ((float*)swv)[tid - 72]  = ca_w_in[16 * EE + (tid - 72)];
    else if (tid < 144) sbv[tid - 136]           = ca_b_in[16 + (tid - 136)];
    else if (tid < 208) ((float*)swo)[tid - 144] = ca_w_out[tid - 144];
    else if (tid < 216) sbo[tid - 208]           = ca_b_out[tid - 208];
    srw1[tid]       = r_w1[tid];
    srw1[tid + 256] = r_w1[tid + 256];
    if (tid < 16) { srb1[tid] = r_b1[tid]; srw2[tid] = r_w2[tid]; }
    __syncthreads();

    // ---- cross-attention scores: ssc[fh][s] = x[s].A[fh] + c[fh] ----
#pragma unroll
    for (int j = 0; j < 2; j++) {
        int s = tid + 256 * j;
        float4 x0 = sx4[s * 2], x1 = sx4[s * 2 + 1];
#pragma unroll
        for (int fh = 0; fh < FH; fh++) {
            float v = scc[fh]
                + sA[fh][0] * x0.x + sA[fh][1] * x0.y + sA[fh][2] * x0.z + sA[fh][3] * x0.w
                + sA[fh][4] * x1.x + sA[fh][5] * x1.y + sA[fh][6] * x1.z + sA[fh][7] * x1.w;
            ssc[fh][s] = v;
        }
    }
    __syncthreads();

    // ---- softmax over s + weighted-x accumulation (one warp per (f,h) row) ----
    {
        float mx = -1e30f;
#pragma unroll
        for (int i = 0; i < 16; i++) mx = fmaxf(mx, ssc[w][lane + 32 * i]);
#pragma unroll
        for (int o = 16; o > 0; o >>= 1) mx = fmaxf(mx, __shfl_xor_sync(~0u, mx, o));
        float sum = 0.f;
        float acc[8] = {0.f, 0.f, 0.f, 0.f, 0.f, 0.f, 0.f, 0.f};
#pragma unroll
        for (int i = 0; i < 16; i++) {
            int s = lane + 32 * i;
            float e = __expf(ssc[w][s] - mx);
            sum += e;
            float4 x0 = sx4[s * 2], x1 = sx4[s * 2 + 1];
            acc[0] += e * x0.x; acc[1] += e * x0.y; acc[2] += e * x0.z; acc[3] += e * x0.w;
            acc[4] += e * x1.x; acc[5] += e * x1.y; acc[6] += e * x1.z; acc[7] += e * x1.w;
        }
#pragma unroll
        for (int o = 16; o > 0; o >>= 1) {
            sum += __shfl_xor_sync(~0u, sum, o);
#pragma unroll
            for (int e = 0; e < 8; e++) acc[e] += __shfl_xor_sync(~0u, acc[e], o);
        }
        if (lane == 0) {
            // ctx[f, h*4+d] = (sum_e acc_e * wv[h*4+d, e]) / sum + bv[h*4+d]
            float inv = 1.0f / sum;
            int f = w >> 1, h = w & 1;
#pragma unroll
            for (int d = 0; d < 4; d++) {
                int r = h * 4 + d;
                float a = 0.f;
#pragma unroll
                for (int e = 0; e < 8; e++) a += acc[e] * swv[r][e];
                sctx[f][r] = a * inv + sbv[r];
            }
        }
    }
    __syncthreads();

    // ---- Q_cross = ctx @ w_out^T + b_out ----
    if (tid < 32) {
        int f = tid >> 3, ep = tid & 7;
        float a = sbo[ep];
#pragma unroll
        for (int e = 0; e < 8; e++) a += sctx[f][e] * swo[ep][e];
        sqc[f][ep] = a;
    }
    __syncthreads();

    // ---- similarity[f][s] = Q_cross[f] . x[s] -> smem (reuse ssc) + gmem ----
    float* ssim = &ssc[0][0];  // [FF][SS]
    float4* __restrict__ simOut = (float4*)(sim + (size_t)b * (FF * SS));
#pragma unroll
    for (int j = 0; j < 2; j++) {
        int v = tid + 256 * j;       // float4 index over F*S/4 = 512
        int f = v >> 7;              // 128 float4 per f
        int s0 = (v & 127) * 4;
        float q0 = sqc[f][0], q1 = sqc[f][1], q2 = sqc[f][2], q3 = sqc[f][3];
        float q4 = sqc[f][4], q5 = sqc[f][5], q6 = sqc[f][6], q7 = sqc[f][7];
        float4 r;
        float* rp = &r.x;
#pragma unroll
        for (int k = 0; k < 4; k++) {
            int s = s0 + k;
            float4 x0 = sx4[s * 2], x1 = sx4[s * 2 + 1];
            rp[k] = q0 * x0.x + q1 * x0.y + q2 * x0.z + q3 * x0.w
                  + q4 * x1.x + q5 * x1.y + q6 * x1.z + q7 * x1.w;
        }
        ((float4*)ssim)[v] = r;
        simOut[v] = r;
    }
    __syncthreads();

    // ---- final softmax over s (one warp per f) + weighted-x ----
    if (w < FF) {
        float mx = -1e30f;
#pragma unroll
        for (int i = 0; i < 16; i++) mx = fmaxf(mx, ssim[w * SS + lane + 32 * i]);
#pragma unroll
        for (int o = 16; o > 0; o >>= 1) mx = fmaxf(mx, __shfl_xor_sync(~0u, mx, o));
        float sum = 0.f;
        float acc[8] = {0.f, 0.f, 0.f, 0.f, 0.f, 0.f, 0.f, 0.f};
#pragma unroll
        for (int i = 0; i < 16; i++) {
            int s = lane + 32 * i;
            float e = __expf(ssim[w * SS + s] - mx);
            sum += e;
            float4 x0 = sx4[s * 2], x1 = sx4[s * 2 + 1];
            acc[0] += e * x0.x; acc[1] += e * x0.y; acc[2] += e * x0.z; acc[3] += e * x0.w;
            acc[4] += e * x1.x; acc[5] += e * x1.y; acc[6] += e * x1.z; acc[7] += e * x1.w;
        }
#pragma unroll
        for (int o = 16; o > 0; o >>= 1) {
            sum += __shfl_xor_sync(~0u, sum, o);
#pragma unroll
            for (int e = 0; e < 8; e++) acc[e] += __shfl_xor_sync(~0u, acc[e], o);
        }
        if (lane == 0) {
            float inv = 1.0f / sum;
#pragma unroll
            for (int e = 0; e < 8; e++) sfin[w][e] = acc[e] * inv;
        }
    }
    __syncthreads();

    // ---- tiny MLP head: out = relu(fused @ w1^T + b1) @ w2^T + b2 ----
    if (tid < 32) {
        float hi = 0.f;
        if (tid < 16) {
            float a = srb1[tid];
            const float* fused = (const float*)sfin;  // [f*8+e] order
#pragma unroll
            for (int j = 0; j < 32; j++) a += fused[j] * srw1[tid * 32 + j];
            hi = fmaxf(a, 0.f) * srw2[tid];
        }
#pragma unroll
        for (int o = 16; o > 0; o >>= 1) hi += __shfl_xor_sync(~0u, hi, o);
        if (tid == 0) outv[b] = hi + r_b2[0];
    }
}

extern "C" void kernel_launch(void* const* d_in, const int* in_sizes, int n_in,
                              void* d_out, int out_size) {
    const float* x        = (const float*)d_in[0];
    const float* Q        = (const float*)d_in[1];
    const float* sa_w_in  = (const float*)d_in[2];
    const float* sa_b_in  = (const float*)d_in[3];
    const float* sa_w_out = (const float*)d_in[4];
    const float* sa_b_out = (const float*)d_in[5];
    const float* ca_w_in  = (const float*)d_in[6];
    const float* ca_b_in  = (const float*)d_in[7];
    const float* ca_w_out = (const float*)d_in[8];
    const float* ca_b_out = (const float*)d_in[9];
    const float* r_w1     = (const float*)d_in[10];
    const float* r_b1     = (const float*)d_in[11];
    const float* r_w2     = (const float*)d_in[12];
    const float* r_b2     = (const float*)d_in[13];

    int B = in_sizes[0] / (SS * EE);
    float* outv = (float*)d_out;          // [B] first return value
    float* sim  = outv + B;               // [B, F, S] second return value

    precompute_kernel<<<1, 1>>>(Q, sa_w_in, sa_b_in, sa_w_out, sa_b_out, ca_w_in, ca_b_in);
    afs_main_kernel<<<B, 256>>>(x, ca_w_in, ca_b_in, ca_w_out, ca_b_out,
                                r_w1, r_b1, r_w2, r_b2, outv, sim);
}

// round 3
// speedup vs baseline: 1.4789x; 1.4789x over previous
#include <cuda_runtime.h>

#define SS 512
#define EE 8
#define FF 4
#define FH 8   // F * num_heads

// Batch-independent precomputed cross-attention query-side terms:
// score[f,h,s] = x[s,:] . g_A[f*2+h,:] + g_c[f*2+h]
__device__ float g_A[FH][EE];
__device__ float g_c[FH];

__global__ void precompute_kernel(const float* __restrict__ Q,
                                  const float* __restrict__ sa_w_in,
                                  const float* __restrict__ sa_b_in,
                                  const float* __restrict__ sa_w_out,
                                  const float* __restrict__ sa_b_out,
                                  const float* __restrict__ ca_w_in,
                                  const float* __restrict__ ca_b_in) {
    float qh[FF][EE], kh[FF][EE], vh[FF][EE];
    for (int f = 0; f < FF; f++)
        for (int ep = 0; ep < EE; ep++) {
            float aq = sa_b_in[ep], ak = sa_b_in[8 + ep], av = sa_b_in[16 + ep];
            for (int e = 0; e < EE; e++) {
                float qe = Q[f * EE + e];
                aq += qe * sa_w_in[ep * EE + e];
                ak += qe * sa_w_in[(8 + ep) * EE + e];
                av += qe * sa_w_in[(16 + ep) * EE + e];
            }
            qh[f][ep] = aq; kh[f][ep] = ak; vh[f][ep] = av;
        }
    float ctx[FF][EE];
    for (int h = 0; h < 2; h++)
        for (int f = 0; f < FF; f++) {
            float sc[FF];
            float mx = -1e30f;
            for (int m = 0; m < FF; m++) {
                float s = 0.f;
                for (int d = 0; d < 4; d++) s += qh[f][h * 4 + d] * kh[m][h * 4 + d];
                s *= 0.5f;
                sc[m] = s;
                mx = fmaxf(mx, s);
            }
            float sum = 0.f;
            for (int m = 0; m < FF; m++) { sc[m] = expf(sc[m] - mx); sum += sc[m]; }
            for (int d = 0; d < 4; d++) {
                float a = 0.f;
                for (int m = 0; m < FF; m++) a += sc[m] * vh[m][h * 4 + d];
                ctx[f][h * 4 + d] = a / sum;
            }
        }
    float qu[FF][EE];
    for (int f = 0; f < FF; f++)
        for (int ep = 0; ep < EE; ep++) {
            float a = sa_b_out[ep];
            for (int e = 0; e < EE; e++) a += ctx[f][e] * sa_w_out[ep * EE + e];
            qu[f][ep] = a;
        }
    float qc[FF][EE];
    for (int f = 0; f < FF; f++)
        for (int ep = 0; ep < EE; ep++) {
            float a = ca_b_in[ep];
            for (int e = 0; e < EE; e++) a += qu[f][e] * ca_w_in[ep * EE + e];
            qc[f][ep] = a * 0.5f;
        }
    for (int f = 0; f < FF; f++)
        for (int h = 0; h < 2; h++) {
            float c = 0.f;
            for (int d = 0; d < 4; d++) c += qc[f][h * 4 + d] * ca_b_in[8 + h * 4 + d];
            g_c[f * 2 + h] = c;
            for (int e = 0; e < EE; e++) {
                float a = 0.f;
                for (int d = 0; d < 4; d++) a += qc[f][h * 4 + d] * ca_w_in[(8 + h * 4 + d) * EE + e];
                g_A[f * 2 + h][e] = a;
            }
        }
}

__global__ __launch_bounds__(256, 3) void afs_main_kernel(
    const float* __restrict__ x,
    const float* __restrict__ ca_w_in, const float* __restrict__ ca_b_in,
    const float* __restrict__ ca_w_out, const float* __restrict__ ca_b_out,
    const float* __restrict__ r_w1, const float* __restrict__ r_b1,
    const float* __restrict__ r_w2, const float* __restrict__ r_b2,
    float* __restrict__ outv, float* __restrict__ sim)
{
    // partial buffers: 32 partial-slots (8 warps x 4 groups), rows of 12 per fh, padded
    __shared__ float pacc[32][100];     // [part][fh*12 + k], k<9 used
    __shared__ float pmax[8][8];        // per-warp per-row max partials
    __shared__ float gmax[8];
    __shared__ float gmax2[4];
    __shared__ float red[80];           // reduced entries (72 / 36)
    __shared__ float sA[8][8];
    __shared__ float scc[8];
    __shared__ float swv[8][8];
    __shared__ float sbv[8];
    __shared__ float swo[8][8];
    __shared__ float sbo[8];
    __shared__ float sqc[32];
    __shared__ float sctx[32];
    __shared__ float sfin[32];
    __shared__ float srw1[16 * 33];     // padded stride 33 (bank-conflict free)
    __shared__ float srb1[16];
    __shared__ float srw2[16];

    const int tid = threadIdx.x;
    const int b = blockIdx.x;
    const int w = tid >> 5, lane = tid & 31;
    const int part = w * 4 + (lane >> 3);
    const bool leader = (lane & 7) == 0;

    // ---- load x rows s=tid and s=tid+256 into registers (never touches smem) ----
    const float4* __restrict__ xin = (const float4*)(x + (size_t)b * (SS * EE));
    float x0[8], x1[8];
    {
        float4 a0 = xin[2 * tid],        a1 = xin[2 * tid + 1];
        float4 b0 = xin[2 * (tid + 256)], b1 = xin[2 * (tid + 256) + 1];
        x0[0] = a0.x; x0[1] = a0.y; x0[2] = a0.z; x0[3] = a0.w;
        x0[4] = a1.x; x0[5] = a1.y; x0[6] = a1.z; x0[7] = a1.w;
        x1[0] = b0.x; x1[1] = b0.y; x1[2] = b0.z; x1[3] = b0.w;
        x1[4] = b1.x; x1[5] = b1.y; x1[6] = b1.z; x1[7] = b1.w;
    }

    // ---- small weights to smem ----
    if (tid < 64)       ((float*)sA)[tid]        = ((const float*)g_A)[tid];
    else if (tid < 72)  scc[tid - 64]            = g_c[tid - 64];
    else if (tid < 136) ((float*)swv)[tid - 72]  = ca_w_in[16 * EE + (tid - 72)];
    else if (tid < 144) sbv[tid - 136]           = ca_b_in[16 + (tid - 136)];
    else if (tid < 208) ((float*)swo)[tid - 144] = ca_w_out[tid - 144];
    else if (tid < 216) sbo[tid - 208]           = ca_b_out[tid - 208];
    else if (tid < 232) srb1[tid - 216]          = r_b1[tid - 216];
    else if (tid < 248) srw2[tid - 232]          = r_w2[tid - 232];
#pragma unroll
    for (int i = tid; i < 512; i += 256) srw1[(i >> 5) * 33 + (i & 31)] = r_w1[i];
    __syncthreads();

    // ---- P1: cross-attn scores for both owned s rows, all 8 (f,h) rows ----
    float sc0[8], sc1[8];
#pragma unroll
    for (int fh = 0; fh < 8; fh++) {
        float4 A0 = *(const float4*)&sA[fh][0];
        float4 A1 = *(const float4*)&sA[fh][4];
        float c = scc[fh];
        sc0[fh] = c + A0.x * x0[0] + A0.y * x0[1] + A0.z * x0[2] + A0.w * x0[3]
                    + A1.x * x0[4] + A1.y * x0[5] + A1.z * x0[6] + A1.w * x0[7];
        sc1[fh] = c + A0.x * x1[0] + A0.y * x1[1] + A0.z * x1[2] + A0.w * x1[3]
                    + A1.x * x1[4] + A1.y * x1[5] + A1.z * x1[6] + A1.w * x1[7];
    }

    // ---- P2: block max per fh ----
#pragma unroll
    for (int fh = 0; fh < 8; fh++) {
        float m = fmaxf(sc0[fh], sc1[fh]);
#pragma unroll
        for (int o = 16; o > 0; o >>= 1) m = fmaxf(m, __shfl_xor_sync(~0u, m, o));
        if (lane == 0) pmax[w][fh] = m;
    }
    __syncthreads();
    if (tid < 8) {
        float g = pmax[0][tid];
#pragma unroll
        for (int ww = 1; ww < 8; ww++) g = fmaxf(g, pmax[ww][tid]);
        gmax[tid] = g;
    }
    __syncthreads();

    // ---- P3/P4: exp weights + partial (acc[8e], sum) per fh; 3-level warp reduce ----
#pragma unroll
    for (int fh = 0; fh < 8; fh++) {
        float g = gmax[fh];
        float w0 = __expf(sc0[fh] - g);
        float w1 = __expf(sc1[fh] - g);
        float p[9];
#pragma unroll
        for (int e = 0; e < 8; e++) p[e] = w0 * x0[e] + w1 * x1[e];
        p[8] = w0 + w1;
#pragma unroll
        for (int o = 1; o <= 4; o <<= 1)
#pragma unroll
            for (int k = 0; k < 9; k++) p[k] += __shfl_xor_sync(~0u, p[k], o);
        if (leader) {
            *(float4*)&pacc[part][fh * 12 + 0] = make_float4(p[0], p[1], p[2], p[3]);
            *(float4*)&pacc[part][fh * 12 + 4] = make_float4(p[4], p[5], p[6], p[7]);
            pacc[part][fh * 12 + 8] = p[8];
        }
    }
    __syncthreads();

    // ---- P5: warp 0 finalizes acc -> ctx -> Q_cross ----
    if (w == 0) {
#pragma unroll
        for (int rep = 0; rep < 3; rep++) {
            int ent = lane + 32 * rep;
            if (ent < 72) {
                int fh = ent / 9, k = ent % 9;
                float s = 0.f;
#pragma unroll
                for (int p = 0; p < 32; p++) s += pacc[p][fh * 12 + k];
                red[ent] = s;
            }
        }
        __syncwarp();
        {
            int f = lane >> 3, r = lane & 7;
            int fh = f * 2 + (r >> 2);
            float inv = 1.0f / red[fh * 9 + 8];
            float a = 0.f;
#pragma unroll
            for (int e = 0; e < 8; e++) a += red[fh * 9 + e] * swv[r][e];
            sctx[lane] = a * inv + sbv[r];
        }
        __syncwarp();
        {
            int f = lane >> 3, ep = lane & 7;
            float a = sbo[ep];
#pragma unroll
            for (int e = 0; e < 8; e++) a += sctx[f * 8 + e] * swo[ep][e];
            sqc[f * 8 + ep] = a;
        }
    }
    __syncthreads();

    // ---- P6: similarity for owned s rows (from register x), write to gmem ----
    float s0[4], s1[4];
    float* __restrict__ simo = sim + (size_t)b * (FF * SS);
#pragma unroll
    for (int f = 0; f < 4; f++) {
        float4 q0 = *(const float4*)&sqc[f * 8];
        float4 q1 = *(const float4*)&sqc[f * 8 + 4];
        s0[f] = q0.x * x0[0] + q0.y * x0[1] + q0.z * x0[2] + q0.w * x0[3]
              + q1.x * x0[4] + q1.y * x0[5] + q1.z * x0[6] + q1.w * x0[7];
        s1[f] = q0.x * x1[0] + q0.y * x1[1] + q0.z * x1[2] + q0.w * x1[3]
              + q1.x * x1[4] + q1.y * x1[5] + q1.z * x1[6] + q1.w * x1[7];
        simo[f * SS + tid]       = s0[f];
        simo[f * SS + tid + 256] = s1[f];
    }

    // ---- P7: final softmax over s per f + weighted-x partials ----
#pragma unroll
    for (int f = 0; f < 4; f++) {
        float m = fmaxf(s0[f], s1[f]);
#pragma unroll
        for (int o = 16; o > 0; o >>= 1) m = fmaxf(m, __shfl_xor_sync(~0u, m, o));
        if (lane == 0) pmax[w][f] = m;
    }
    __syncthreads();
    if (tid < 4) {
        float g = pmax[0][tid];
#pragma unroll
        for (int ww = 1; ww < 8; ww++) g = fmaxf(g, pmax[ww][tid]);
        gmax2[tid] = g;
    }
    __syncthreads();
#pragma unroll
    for (int f = 0; f < 4; f++) {
        float g = gmax2[f];
        float w0 = __expf(s0[f] - g);
        float w1 = __expf(s1[f] - g);
        float p[9];
#pragma unroll
        for (int e = 0; e < 8; e++) p[e] = w0 * x0[e] + w1 * x1[e];
        p[8] = w0 + w1;
#pragma unroll
        for (int o = 1; o <= 4; o <<= 1)
#pragma unroll
            for (int k = 0; k < 9; k++) p[k] += __shfl_xor_sync(~0u, p[k], o);
        if (leader) {
            *(float4*)&pacc[part][f * 12 + 0] = make_float4(p[0], p[1], p[2], p[3]);
            *(float4*)&pacc[part][f * 12 + 4] = make_float4(p[4], p[5], p[6], p[7]);
            pacc[part][f * 12 + 8] = p[8];
        }
    }
    __syncthreads();

    // ---- P8: warp 0 finalizes final factors + MLP head ----
    if (w == 0) {
#pragma unroll
        for (int rep = 0; rep < 2; rep++) {
            int ent = lane + 32 * rep;
            if (ent < 36) {
                int f = ent / 9, k = ent % 9;
                float s = 0.f;
#pragma unroll
                for (int p = 0; p < 32; p++) s += pacc[p][f * 12 + k];
                red[ent] = s;
            }
        }
        __syncwarp();
        {
            int f = lane >> 3, e = lane & 7;
            sfin[lane] = red[f * 9 + e] / red[f * 9 + 8];
        }
        __syncwarp();
        float v = 0.f;
        if (lane < 16) {
            float a = srb1[lane];
#pragma unroll
            for (int j = 0; j < 32; j++) a += sfin[j] * srw1[lane * 33 + j];
            v = fmaxf(a, 0.f) * srw2[lane];
        }
#pragma unroll
        for (int o = 16; o > 0; o >>= 1) v += __shfl_xor_sync(~0u, v, o);
        if (lane == 0) outv[b] = v + r_b2[0];
    }
}

extern "C" void kernel_launch(void* const* d_in, const int* in_sizes, int n_in,
                              void* d_out, int out_size) {
    const float* x        = (const float*)d_in[0];
    const float* Q        = (const float*)d_in[1];
    const float* sa_w_in  = (const float*)d_in[2];
    const float* sa_b_in  = (const float*)d_in[3];
    const float* sa_w_out = (const float*)d_in[4];
    const float* sa_b_out = (const float*)d_in[5];
    const float* ca_w_in  = (const float*)d_in[6];
    const float* ca_b_in  = (const float*)d_in[7];
    const float* ca_w_out = (const float*)d_in[8];
    const float* ca_b_out = (const float*)d_in[9];
    const float* r_w1     = (const float*)d_in[10];
    const float* r_b1     = (const float*)d_in[11];
    const float* r_w2     = (const float*)d_in[12];
    const float* r_b2     = (const float*)d_in[13];

    int B = in_sizes[0] / (SS * EE);
    float* outv = (float*)d_out;          // [B] first return value
    float* sim  = outv + B;               // [B, F, S] second return value

    precompute_kernel<<<1, 1>>>(Q, sa_w_in, sa_b_in, sa_w_out, sa_b_out, ca_w_in, ca_b_in);
    afs_main_kernel<<<B, 256>>>(x, ca_w_in, ca_b_in, ca_w_out, ca_b_out,
                                r_w1, r_b1, r_w2, r_b2, outv, sim);
}

// round 4
// speedup vs baseline: 1.4837x; 1.0032x over previous
#include <cuda_runtime.h>

#define SS 512
#define EE 8
#define FF 4
#define FH 8   // F * num_heads

// Batch-independent precomputed cross-attention query-side terms:
// score[f,h,s] = x[s,:] . g_A[f*2+h,:] + g_c[f*2+h]
__device__ float g_A[FH][EE];
__device__ float g_c[FH];

__global__ void precompute_kernel(const float* __restrict__ Q,
                                  const float* __restrict__ sa_w_in,
                                  const float* __restrict__ sa_b_in,
                                  const float* __restrict__ sa_w_out,
                                  const float* __restrict__ sa_b_out,
                                  const float* __restrict__ ca_w_in,
                                  const float* __restrict__ ca_b_in) {
    float qh[FF][EE], kh[FF][EE], vh[FF][EE];
    for (int f = 0; f < FF; f++)
        for (int ep = 0; ep < EE; ep++) {
            float aq = sa_b_in[ep], ak = sa_b_in[8 + ep], av = sa_b_in[16 + ep];
            for (int e = 0; e < EE; e++) {
                float qe = Q[f * EE + e];
                aq += qe * sa_w_in[ep * EE + e];
                ak += qe * sa_w_in[(8 + ep) * EE + e];
                av += qe * sa_w_in[(16 + ep) * EE + e];
            }
            qh[f][ep] = aq; kh[f][ep] = ak; vh[f][ep] = av;
        }
    float ctx[FF][EE];
    for (int h = 0; h < 2; h++)
        for (int f = 0; f < FF; f++) {
            float sc[FF];
            float mx = -1e30f;
            for (int m = 0; m < FF; m++) {
                float s = 0.f;
                for (int d = 0; d < 4; d++) s += qh[f][h * 4 + d] * kh[m][h * 4 + d];
                s *= 0.5f;
                sc[m] = s;
                mx = fmaxf(mx, s);
            }
            float sum = 0.f;
            for (int m = 0; m < FF; m++) { sc[m] = expf(sc[m] - mx); sum += sc[m]; }
            for (int d = 0; d < 4; d++) {
                float a = 0.f;
                for (int m = 0; m < FF; m++) a += sc[m] * vh[m][h * 4 + d];
                ctx[f][h * 4 + d] = a / sum;
            }
        }
    float qu[FF][EE];
    for (int f = 0; f < FF; f++)
        for (int ep = 0; ep < EE; ep++) {
            float a = sa_b_out[ep];
            for (int e = 0; e < EE; e++) a += ctx[f][e] * sa_w_out[ep * EE + e];
            qu[f][ep] = a;
        }
    float qc[FF][EE];
    for (int f = 0; f < FF; f++)
        for (int ep = 0; ep < EE; ep++) {
            float a = ca_b_in[ep];
            for (int e = 0; e < EE; e++) a += qu[f][e] * ca_w_in[ep * EE + e];
            qc[f][ep] = a * 0.5f;
        }
    for (int f = 0; f < FF; f++)
        for (int h = 0; h < 2; h++) {
            float c = 0.f;
            for (int d = 0; d < 4; d++) c += qc[f][h * 4 + d] * ca_b_in[8 + h * 4 + d];
            g_c[f * 2 + h] = c;
            for (int e = 0; e < EE; e++) {
                float a = 0.f;
                for (int d = 0; d < 4; d++) a += qc[f][h * 4 + d] * ca_w_in[(8 + h * 4 + d) * EE + e];
                g_A[f * 2 + h][e] = a;
            }
        }
}

__global__ __launch_bounds__(256, 3) void afs_main_kernel(
    const float* __restrict__ x,
    const float* __restrict__ ca_w_in, const float* __restrict__ ca_b_in,
    const float* __restrict__ ca_w_out, const float* __restrict__ ca_b_out,
    const float* __restrict__ r_w1, const float* __restrict__ r_b1,
    const float* __restrict__ r_w2, const float* __restrict__ r_b2,
    float* __restrict__ outv, float* __restrict__ sim)
{
    // partial buffers: 32 partial-slots (8 warps x 4 groups), rows of 12 per fh, padded
    __shared__ float pacc[32][100];     // [part][fh*12 + k], k<9 used
    __shared__ float pmax[8][8];        // per-warp per-row max partials
    __shared__ float gmax[8];
    __shared__ float gmax2[4];
    __shared__ float red[80];           // reduced entries (72 / 36)
    __shared__ float sA[8][8];
    __shared__ float scc[8];
    __shared__ float swv[8][8];
    __shared__ float sbv[8];
    __shared__ float swo[8][8];
    __shared__ float sbo[8];
    __shared__ float sqc[32];
    __shared__ float sctx[32];
    __shared__ float sfin[32];
    __shared__ float srw1[16 * 33];     // padded stride 33 (bank-conflict free)
    __shared__ float srb1[16];
    __shared__ float srw2[16];

    const int tid = threadIdx.x;
    const int b = blockIdx.x;
    const int w = tid >> 5, lane = tid & 31;
    const int part = w * 4 + (lane >> 3);
    const bool leader = (lane & 7) == 0;

    // ---- load x rows s=tid and s=tid+256 into registers (never touches smem) ----
    const float4* __restrict__ xin = (const float4*)(x + (size_t)b * (SS * EE));
    float x0[8], x1[8];
    {
        float4 a0 = xin[2 * tid],        a1 = xin[2 * tid + 1];
        float4 b0 = xin[2 * (tid + 256)], b1 = xin[2 * (tid + 256) + 1];
        x0[0] = a0.x; x0[1] = a0.y; x0[2] = a0.z; x0[3] = a0.w;
        x0[4] = a1.x; x0[5] = a1.y; x0[6] = a1.z; x0[7] = a1.w;
        x1[0] = b0.x; x1[1] = b0.y; x1[2] = b0.z; x1[3] = b0.w;
        x1[4] = b1.x; x1[5] = b1.y; x1[6] = b1.z; x1[7] = b1.w;
    }

    // ---- small weights to smem ----
    if (tid < 64)       ((float*)sA)[tid]        = ((const float*)g_A)[tid];
    else if (tid < 72)  scc[tid - 64]            = g_c[tid - 64];
    else if (tid < 136) ((float*)swv)[tid - 72]  = ca_w_in[16 * EE + (tid - 72)];
    else if (tid < 144) sbv[tid - 136]           = ca_b_in[16 + (tid - 136)];
    else if (tid < 208) ((float*)swo)[tid - 144] = ca_w_out[tid - 144];
    else if (tid < 216) sbo[tid - 208]           = ca_b_out[tid - 208];
    else if (tid < 232) srb1[tid - 216]          = r_b1[tid - 216];
    else if (tid < 248) srw2[tid - 232]          = r_w2[tid - 232];
#pragma unroll
    for (int i = tid; i < 512; i += 256) srw1[(i >> 5) * 33 + (i & 31)] = r_w1[i];
    __syncthreads();

    // ---- P1: cross-attn scores for both owned s rows, all 8 (f,h) rows ----
    float sc0[8], sc1[8];
#pragma unroll
    for (int fh = 0; fh < 8; fh++) {
        float4 A0 = *(const float4*)&sA[fh][0];
        float4 A1 = *(const float4*)&sA[fh][4];
        float c = scc[fh];
        sc0[fh] = c + A0.x * x0[0] + A0.y * x0[1] + A0.z * x0[2] + A0.w * x0[3]
                    + A1.x * x0[4] + A1.y * x0[5] + A1.z * x0[6] + A1.w * x0[7];
        sc1[fh] = c + A0.x * x1[0] + A0.y * x1[1] + A0.z * x1[2] + A0.w * x1[3]
                    + A1.x * x1[4] + A1.y * x1[5] + A1.z * x1[6] + A1.w * x1[7];
    }

    // ---- P2: block max per fh ----
#pragma unroll
    for (int fh = 0; fh < 8; fh++) {
        float m = fmaxf(sc0[fh], sc1[fh]);
#pragma unroll
        for (int o = 16; o > 0; o >>= 1) m = fmaxf(m, __shfl_xor_sync(~0u, m, o));
        if (lane == 0) pmax[w][fh] = m;
    }
    __syncthreads();
    if (tid < 8) {
        float g = pmax[0][tid];
#pragma unroll
        for (int ww = 1; ww < 8; ww++) g = fmaxf(g, pmax[ww][tid]);
        gmax[tid] = g;
    }
    __syncthreads();

    // ---- P3/P4: exp weights + partial (acc[8e], sum) per fh; 3-level warp reduce ----
#pragma unroll
    for (int fh = 0; fh < 8; fh++) {
        float g = gmax[fh];
        float w0 = __expf(sc0[fh] - g);
        float w1 = __expf(sc1[fh] - g);
        float p[9];
#pragma unroll
        for (int e = 0; e < 8; e++) p[e] = w0 * x0[e] + w1 * x1[e];
        p[8] = w0 + w1;
#pragma unroll
        for (int o = 1; o <= 4; o <<= 1)
#pragma unroll
            for (int k = 0; k < 9; k++) p[k] += __shfl_xor_sync(~0u, p[k], o);
        if (leader) {
            *(float4*)&pacc[part][fh * 12 + 0] = make_float4(p[0], p[1], p[2], p[3]);
            *(float4*)&pacc[part][fh * 12 + 4] = make_float4(p[4], p[5], p[6], p[7]);
            pacc[part][fh * 12 + 8] = p[8];
        }
    }
    __syncthreads();

    // ---- P5: warp 0 finalizes acc -> ctx -> Q_cross ----
    if (w == 0) {
#pragma unroll
        for (int rep = 0; rep < 3; rep++) {
            int ent = lane + 32 * rep;
            if (ent < 72) {
                int fh = ent / 9, k = ent % 9;
                float s = 0.f;
#pragma unroll
                for (int p = 0; p < 32; p++) s += pacc[p][fh * 12 + k];
                red[ent] = s;
            }
        }
        __syncwarp();
        {
            int f = lane >> 3, r = lane & 7;
            int fh = f * 2 + (r >> 2);
            float inv = 1.0f / red[fh * 9 + 8];
            float a = 0.f;
#pragma unroll
            for (int e = 0; e < 8; e++) a += red[fh * 9 + e] * swv[r][e];
            sctx[lane] = a * inv + sbv[r];
        }
        __syncwarp();
        {
            int f = lane >> 3, ep = lane & 7;
            float a = sbo[ep];
#pragma unroll
            for (int e = 0; e < 8; e++) a += sctx[f * 8 + e] * swo[ep][e];
            sqc[f * 8 + ep] = a;
        }
    }
    __syncthreads();

    // ---- P6: similarity for owned s rows (from register x), write to gmem ----
    float s0[4], s1[4];
    float* __restrict__ simo = sim + (size_t)b * (FF * SS);
#pragma unroll
    for (int f = 0; f < 4; f++) {
        float4 q0 = *(const float4*)&sqc[f * 8];
        float4 q1 = *(const float4*)&sqc[f * 8 + 4];
        s0[f] = q0.x * x0[0] + q0.y * x0[1] + q0.z * x0[2] + q0.w * x0[3]
              + q1.x * x0[4] + q1.y * x0[5] + q1.z * x0[6] + q1.w * x0[7];
        s1[f] = q0.x * x1[0] + q0.y * x1[1] + q0.z * x1[2] + q0.w * x1[3]
              + q1.x * x1[4] + q1.y * x1[5] + q1.z * x1[6] + q1.w * x1[7];
        simo[f * SS + tid]       = s0[f];
        simo[f * SS + tid + 256] = s1[f];
    }

    // ---- P7: final softmax over s per f + weighted-x partials ----
#pragma unroll
    for (int f = 0; f < 4; f++) {
        float m = fmaxf(s0[f], s1[f]);
#pragma unroll
        for (int o = 16; o > 0; o >>= 1) m = fmaxf(m, __shfl_xor_sync(~0u, m, o));
        if (lane == 0) pmax[w][f] = m;
    }
    __syncthreads();
    if (tid < 4) {
        float g = pmax[0][tid];
#pragma unroll
        for (int ww = 1; ww < 8; ww++) g = fmaxf(g, pmax[ww][tid]);
        gmax2[tid] = g;
    }
    __syncthreads();
#pragma unroll
    for (int f = 0; f < 4; f++) {
        float g = gmax2[f];
        float w0 = __expf(s0[f] - g);
        float w1 = __expf(s1[f] - g);
        float p[9];
#pragma unroll
        for (int e = 0; e < 8; e++) p[e] = w0 * x0[e] + w1 * x1[e];
        p[8] = w0 + w1;
#pragma unroll
        for (int o = 1; o <= 4; o <<= 1)
#pragma unroll
            for (int k = 0; k < 9; k++) p[k] += __shfl_xor_sync(~0u, p[k], o);
        if (leader) {
            *(float4*)&pacc[part][f * 12 + 0] = make_float4(p[0], p[1], p[2], p[3]);
            *(float4*)&pacc[part][f * 12 + 4] = make_float4(p[4], p[5], p[6], p[7]);
            pacc[part][f * 12 + 8] = p[8];
        }
    }
    __syncthreads();

    // ---- P8: warp 0 finalizes final factors + MLP head ----
    if (w == 0) {
#pragma unroll
        for (int rep = 0; rep < 2; rep++) {
            int ent = lane + 32 * rep;
            if (ent < 36) {
                int f = ent / 9, k = ent % 9;
                float s = 0.f;
#pragma unroll
                for (int p = 0; p < 32; p++) s += pacc[p][f * 12 + k];
                red[ent] = s;
            }
        }
        __syncwarp();
        {
            int f = lane >> 3, e = lane & 7;
            sfin[lane] = red[f * 9 + e] / red[f * 9 + 8];
        }
        __syncwarp();
        float v = 0.f;
        if (lane < 16) {
            float a = srb1[lane];
#pragma unroll
            for (int j = 0; j < 32; j++) a += sfin[j] * srw1[lane * 33 + j];
            v = fmaxf(a, 0.f) * srw2[lane];
        }
#pragma unroll
        for (int o = 16; o > 0; o >>= 1) v += __shfl_xor_sync(~0u, v, o);
        if (lane == 0) outv[b] = v + r_b2[0];
    }
}

extern "C" void kernel_launch(void* const* d_in, const int* in_sizes, int n_in,
                              void* d_out, int out_size) {
    const float* x        = (const float*)d_in[0];
    const float* Q        = (const float*)d_in[1];
    const float* sa_w_in  = (const float*)d_in[2];
    const float* sa_b_in  = (const float*)d_in[3];
    const float* sa_w_out = (const float*)d_in[4];
    const float* sa_b_out = (const float*)d_in[5];
    const float* ca_w_in  = (const float*)d_in[6];
    const float* ca_b_in  = (const float*)d_in[7];
    const float* ca_w_out = (const float*)d_in[8];
    const float* ca_b_out = (const float*)d_in[9];
    const float* r_w1     = (const float*)d_in[10];
    const float* r_b1     = (const float*)d_in[11];
    const float* r_w2     = (const float*)d_in[12];
    const float* r_b2     = (const float*)d_in[13];

    int B = in_sizes[0] / (SS * EE);
    float* outv = (float*)d_out;          // [B] first return value
    float* sim  = outv + B;               // [B, F, S] second return value

    precompute_kernel<<<1, 1>>>(Q, sa_w_in, sa_b_in, sa_w_out, sa_b_out, ca_w_in, ca_b_in);
    afs_main_kernel<<<B, 256>>>(x, ca_w_in, ca_b_in, ca_w_out, ca_b_out,
                                r_w1, r_b1, r_w2, r_b2, outv, sim);
}

// round 5
// speedup vs baseline: 2.6337x; 1.7751x over previous
#include <cuda_runtime.h>

#define SS 512
#define EE 8
#define FF 4
#define FH 8   // F * num_heads

// Batch-independent precomputed cross-attention query-side terms:
// score[f,h,s] = x[s,:] . g_A[f*2+h,:] + g_c[f*2+h]
__device__ float g_A[FH][EE];
__device__ float g_c[FH];

__global__ void precompute_kernel(const float* __restrict__ Q,
                                  const float* __restrict__ sa_w_in,
                                  const float* __restrict__ sa_b_in,
                                  const float* __restrict__ sa_w_out,
                                  const float* __restrict__ sa_b_out,
                                  const float* __restrict__ ca_w_in,
                                  const float* __restrict__ ca_b_in) {
    float qh[FF][EE], kh[FF][EE], vh[FF][EE];
    for (int f = 0; f < FF; f++)
        for (int ep = 0; ep < EE; ep++) {
            float aq = sa_b_in[ep], ak = sa_b_in[8 + ep], av = sa_b_in[16 + ep];
            for (int e = 0; e < EE; e++) {
                float qe = Q[f * EE + e];
                aq += qe * sa_w_in[ep * EE + e];
                ak += qe * sa_w_in[(8 + ep) * EE + e];
                av += qe * sa_w_in[(16 + ep) * EE + e];
            }
            qh[f][ep] = aq; kh[f][ep] = ak; vh[f][ep] = av;
        }
    float ctx[FF][EE];
    for (int h = 0; h < 2; h++)
        for (int f = 0; f < FF; f++) {
            float sc[FF];
            float mx = -1e30f;
            for (int m = 0; m < FF; m++) {
                float s = 0.f;
                for (int d = 0; d < 4; d++) s += qh[f][h * 4 + d] * kh[m][h * 4 + d];
                s *= 0.5f;
                sc[m] = s;
                mx = fmaxf(mx, s);
            }
            float sum = 0.f;
            for (int m = 0; m < FF; m++) { sc[m] = expf(sc[m] - mx); sum += sc[m]; }
            for (int d = 0; d < 4; d++) {
                float a = 0.f;
                for (int m = 0; m < FF; m++) a += sc[m] * vh[m][h * 4 + d];
                ctx[f][h * 4 + d] = a / sum;
            }
        }
    float qu[FF][EE];
    for (int f = 0; f < FF; f++)
        for (int ep = 0; ep < EE; ep++) {
            float a = sa_b_out[ep];
            for (int e = 0; e < EE; e++) a += ctx[f][e] * sa_w_out[ep * EE + e];
            qu[f][ep] = a;
        }
    float qc[FF][EE];
    for (int f = 0; f < FF; f++)
        for (int ep = 0; ep < EE; ep++) {
            float a = ca_b_in[ep];
            for (int e = 0; e < EE; e++) a += qu[f][e] * ca_w_in[ep * EE + e];
            qc[f][ep] = a * 0.5f;
        }
    for (int f = 0; f < FF; f++)
        for (int h = 0; h < 2; h++) {
            float c = 0.f;
            for (int d = 0; d < 4; d++) c += qc[f][h * 4 + d] * ca_b_in[8 + h * 4 + d];
            g_c[f * 2 + h] = c;
            for (int e = 0; e < EE; e++) {
                float a = 0.f;
                for (int d = 0; d < 4; d++) a += qc[f][h * 4 + d] * ca_w_in[(8 + h * 4 + d) * EE + e];
                g_A[f * 2 + h][e] = a;
            }
        }
}

// Split-payload warp reduction of 9 values across 32 lanes: 12 SHFL total.
// After the call, the lane's v[0] holds the full-warp sum of ONE entry
// (entry index = 'start', valid when precomputed 'valid' is true).
__device__ __forceinline__ float warp_reduce9(float v[9]) {
    const int lane = threadIdx.x & 31;
    // d=16: n=9, h=5 (entry 9 is a zero pad)
    bool hi = (lane & 16);
#pragma unroll
    for (int i = 0; i < 5; i++) {
        float up = (i + 5 < 9) ? v[i + 5] : 0.f;
        float send = hi ? v[i] : up;
        float t = __shfl_xor_sync(~0u, send, 16);
        v[i] = (hi ? up : v[i]) + t;
    }
    // d=8: n=5, h=3
    hi = (lane & 8);
#pragma unroll
    for (int i = 0; i < 3; i++) {
        float up = (i + 3 < 5) ? v[i + 3] : 0.f;
        float send = hi ? v[i] : up;
        float t = __shfl_xor_sync(~0u, send, 8);
        v[i] = (hi ? up : v[i]) + t;
    }
    // d=4: n=3, h=2
    hi = (lane & 4);
#pragma unroll
    for (int i = 0; i < 2; i++) {
        float up = (i + 2 < 3) ? v[i + 2] : 0.f;
        float send = hi ? v[i] : up;
        float t = __shfl_xor_sync(~0u, send, 4);
        v[i] = (hi ? up : v[i]) + t;
    }
    // d=2: n=2, h=1
    hi = (lane & 2);
    {
        float send = hi ? v[0] : v[1];
        float t = __shfl_xor_sync(~0u, send, 2);
        v[0] = (hi ? v[1] : v[0]) + t;
    }
    // d=1: pair combine (both lanes end with identical full sum)
    v[0] += __shfl_xor_sync(~0u, v[0], 1);
    return v[0];
}

__global__ __launch_bounds__(256, 4) void afs_main_kernel(
    const float* __restrict__ x,
    const float* __restrict__ r_b2,
    float* __restrict__ outv, float* __restrict__ sim,
    const float* __restrict__ ca_w_in, const float* __restrict__ ca_b_in,
    const float* __restrict__ ca_w_out, const float* __restrict__ ca_b_out,
    const float* __restrict__ r_w1, const float* __restrict__ r_b1,
    const float* __restrict__ r_w2)
{
    __shared__ float pacc[8][96];       // [warp][fh*12 + k], k<9 used
    __shared__ float red[80];
    __shared__ float sA[8][8];
    __shared__ float scc[8];
    __shared__ float swv[8][8];
    __shared__ float sbv[8];
    __shared__ float swo[8][8];
    __shared__ float sbo[8];
    __shared__ float sqc[32];
    __shared__ float sctx[32];
    __shared__ float sfin[32];
    __shared__ float srw1[16 * 33];     // padded stride 33
    __shared__ float srb1[16];
    __shared__ float srw2[16];

    const int tid = threadIdx.x;
    const int b = blockIdx.x;
    const int w = tid >> 5, lane = tid & 31;

    // ---- owned-entry bookkeeping for warp_reduce9 (same for every call) ----
    int start = 0, nreal = 9;
    if (lane & 16) { start += 5; nreal -= 5; } else nreal = 5;
    if (lane & 8)  { start += 3; nreal -= 3; } else nreal = (nreal < 3 ? nreal : 3);
    if (lane & 4)  { start += 2; nreal -= 2; } else nreal = (nreal < 2 ? nreal : 2);
    if (lane & 2)  { start += 1; nreal -= 1; } else nreal = (nreal < 1 ? nreal : 1);
    const bool wvalid = (nreal > 0) && !(lane & 1);

    // ---- load x rows s=tid and s=tid+256 into registers ----
    const float4* __restrict__ xin = (const float4*)(x + (size_t)b * (SS * EE));
    float x0[8], x1[8];
    {
        float4 a0 = xin[2 * tid],         a1 = xin[2 * tid + 1];
        float4 b0 = xin[2 * (tid + 256)], b1 = xin[2 * (tid + 256) + 1];
        x0[0] = a0.x; x0[1] = a0.y; x0[2] = a0.z; x0[3] = a0.w;
        x0[4] = a1.x; x0[5] = a1.y; x0[6] = a1.z; x0[7] = a1.w;
        x1[0] = b0.x; x1[1] = b0.y; x1[2] = b0.z; x1[3] = b0.w;
        x1[4] = b1.x; x1[5] = b1.y; x1[6] = b1.z; x1[7] = b1.w;
    }

    // ---- small weights to smem ----
    if (tid < 64)       ((float*)sA)[tid]        = ((const float*)g_A)[tid];
    else if (tid < 72)  scc[tid - 64]            = g_c[tid - 64];
    else if (tid < 136) ((float*)swv)[tid - 72]  = ca_w_in[16 * EE + (tid - 72)];
    else if (tid < 144) sbv[tid - 136]           = ca_b_in[16 + (tid - 136)];
    else if (tid < 208) ((float*)swo)[tid - 144] = ca_w_out[tid - 144];
    else if (tid < 216) sbo[tid - 208]           = ca_b_out[tid - 208];
    else if (tid < 232) srb1[tid - 216]          = r_b1[tid - 216];
    else if (tid < 248) srw2[tid - 232]          = r_w2[tid - 232];
#pragma unroll
    for (int i = tid; i < 512; i += 256) srw1[(i >> 5) * 33 + (i & 31)] = r_w1[i];
    __syncthreads();

    // ---- P1+P3 fused: score -> exp (no max; bounded) -> weighted partials -> reduce ----
#pragma unroll
    for (int fh = 0; fh < 8; fh++) {
        float4 A0 = *(const float4*)&sA[fh][0];
        float4 A1 = *(const float4*)&sA[fh][4];
        float c = scc[fh];
        float sc0 = c + A0.x * x0[0] + A0.y * x0[1] + A0.z * x0[2] + A0.w * x0[3]
                      + A1.x * x0[4] + A1.y * x0[5] + A1.z * x0[6] + A1.w * x0[7];
        float sc1 = c + A0.x * x1[0] + A0.y * x1[1] + A0.z * x1[2] + A0.w * x1[3]
                      + A1.x * x1[4] + A1.y * x1[5] + A1.z * x1[6] + A1.w * x1[7];
        float w0 = __expf(sc0);
        float w1 = __expf(sc1);
        float p[9];
#pragma unroll
        for (int e = 0; e < 8; e++) p[e] = w0 * x0[e] + w1 * x1[e];
        p[8] = w0 + w1;
        float r = warp_reduce9(p);
        if (wvalid) pacc[w][fh * 12 + start] = r;
    }
    __syncthreads();

    // ---- P5: warp 0 combines 8 warps, then ctx -> Q_cross ----
    if (w == 0) {
#pragma unroll
        for (int rep = 0; rep < 3; rep++) {
            int ent = lane + 32 * rep;
            if (ent < 72) {
                int fh = ent / 9, k = ent - fh * 9;
                float s = 0.f;
#pragma unroll
                for (int p = 0; p < 8; p++) s += pacc[p][fh * 12 + k];
                red[ent] = s;
            }
        }
        __syncwarp();
        {
            int f = lane >> 3, r = lane & 7;
            int fh = f * 2 + (r >> 2);
            float inv = 1.0f / red[fh * 9 + 8];
            float a = 0.f;
#pragma unroll
            for (int e = 0; e < 8; e++) a += red[fh * 9 + e] * swv[r][e];
            sctx[lane] = a * inv + sbv[r];
        }
        __syncwarp();
        {
            int f = lane >> 3, ep = lane & 7;
            float a = sbo[ep];
#pragma unroll
            for (int e = 0; e < 8; e++) a += sctx[f * 8 + e] * swo[ep][e];
            sqc[f * 8 + ep] = a;
        }
    }
    __syncthreads();

    // ---- P6+P7 fused: similarity -> gmem, exp (no max) -> partials -> reduce ----
    float* __restrict__ simo = sim + (size_t)b * (FF * SS);
#pragma unroll
    for (int f = 0; f < 4; f++) {
        float4 q0 = *(const float4*)&sqc[f * 8];
        float4 q1 = *(const float4*)&sqc[f * 8 + 4];
        float s0 = q0.x * x0[0] + q0.y * x0[1] + q0.z * x0[2] + q0.w * x0[3]
                 + q1.x * x0[4] + q1.y * x0[5] + q1.z * x0[6] + q1.w * x0[7];
        float s1 = q0.x * x1[0] + q0.y * x1[1] + q0.z * x1[2] + q0.w * x1[3]
                 + q1.x * x1[4] + q1.y * x1[5] + q1.z * x1[6] + q1.w * x1[7];
        simo[f * SS + tid]       = s0;
        simo[f * SS + tid + 256] = s1;
        float w0 = __expf(s0);
        float w1 = __expf(s1);
        float p[9];
#pragma unroll
        for (int e = 0; e < 8; e++) p[e] = w0 * x0[e] + w1 * x1[e];
        p[8] = w0 + w1;
        float r = warp_reduce9(p);
        if (wvalid) pacc[w][f * 12 + start] = r;
    }
    __syncthreads();

    // ---- P8: warp 0 finalizes final factors + MLP head ----
    if (w == 0) {
#pragma unroll
        for (int rep = 0; rep < 2; rep++) {
            int ent = lane + 32 * rep;
            if (ent < 36) {
                int f = ent / 9, k = ent - f * 9;
                float s = 0.f;
#pragma unroll
                for (int p = 0; p < 8; p++) s += pacc[p][f * 12 + k];
                red[ent] = s;
            }
        }
        __syncwarp();
        {
            int f = lane >> 3, e = lane & 7;
            sfin[lane] = red[f * 9 + e] / red[f * 9 + 8];
        }
        __syncwarp();
        float v = 0.f;
        if (lane < 16) {
            float a = srb1[lane];
#pragma unroll
            for (int j = 0; j < 32; j++) a += sfin[j] * srw1[lane * 33 + j];
            v = fmaxf(a, 0.f) * srw2[lane];
        }
#pragma unroll
        for (int o = 16; o > 0; o >>= 1) v += __shfl_xor_sync(~0u, v, o);
        if (lane == 0) outv[b] = v + r_b2[0];
    }
}

extern "C" void kernel_launch(void* const* d_in, const int* in_sizes, int n_in,
                              void* d_out, int out_size) {
    const float* x        = (const float*)d_in[0];
    const float* Q        = (const float*)d_in[1];
    const float* sa_w_in  = (const float*)d_in[2];
    const float* sa_b_in  = (const float*)d_in[3];
    const float* sa_w_out = (const float*)d_in[4];
    const float* sa_b_out = (const float*)d_in[5];
    const float* ca_w_in  = (const float*)d_in[6];
    const float* ca_b_in  = (const float*)d_in[7];
    const float* ca_w_out = (const float*)d_in[8];
    const float* ca_b_out = (const float*)d_in[9];
    const float* r_w1     = (const float*)d_in[10];
    const float* r_b1     = (const float*)d_in[11];
    const float* r_w2     = (const float*)d_in[12];
    const float* r_b2     = (const float*)d_in[13];

    int B = in_sizes[0] / (SS * EE);
    float* outv = (float*)d_out;          // [B] first return value
    float* sim  = outv + B;               // [B, F, S] second return value

    precompute_kernel<<<1, 1>>>(Q, sa_w_in, sa_b_in, sa_w_out, sa_b_out, ca_w_in, ca_b_in);
    afs_main_kernel<<<B, 256>>>(x, r_b2, outv, sim,
                                ca_w_in, ca_b_in, ca_w_out, ca_b_out,
                                r_w1, r_b1, r_w2);
}